// round 2
// baseline (speedup 1.0000x reference)
#include <cuda_runtime.h>
#include <cuda_bf16.h>

// KLDivergence fused single-kernel version.
// pred_map, true_map: [64, 512, 512] fp32.
// KL_b = D_b/S_t_b + ln(S_p_b/S_t_b), with
//   S_p = sum(p+eps), S_t = sum(t+eps), D = sum((t+eps)*(ln(t+eps)-ln(p+eps)))
// D accumulated in log2 units; scaled by ln2 in the finalize.
// Output = mean over 64 batches.

#define KL_EPS 1e-6f
#define LN2F   0.6931471805599453f

static constexpr int B         = 64;
static constexpr int N_PER_B   = 512 * 512;        // 262144
static constexpr int V4_PER_B  = N_PER_B / 4;      // 65536 float4 per batch
static constexpr int CPB       = 16;               // chunks (blocks) per batch
static constexpr int TPB       = 256;
static constexpr int GRID      = B * CPB;          // 1024 blocks
static constexpr int PER_CHUNK = V4_PER_B / CPB;   // 4096 float4 per chunk

// Deterministic scratch: per-(batch,chunk) partials of (S_p, S_t, D_lg2).
__device__ float g_partial[GRID * 3];
__device__ unsigned int g_done = 0;

__device__ __forceinline__ void kl_acc(float p, float t,
                                       float& sp, float& st, float& d) {
    float pp = p + KL_EPS;
    float tt = t + KL_EPS;
    sp += pp;
    st += tt;
    d  += tt * (__log2f(tt) - __log2f(pp));   // ln2 scale deferred to finalize
}

__global__ __launch_bounds__(TPB)
void kl_fused(const float4* __restrict__ pred, const float4* __restrict__ tru,
              float* __restrict__ out, int out_size) {
    const int blk   = blockIdx.x;
    const int batch = blk / CPB;
    const int chunk = blk % CPB;

    const float4* p = pred + (size_t)batch * V4_PER_B + (size_t)chunk * PER_CHUNK;
    const float4* t = tru  + (size_t)batch * V4_PER_B + (size_t)chunk * PER_CHUNK;

    float sp = 0.f, st = 0.f, d = 0.f;

    // 4096 float4 / 256 threads = 16 iterations; unroll 4 for MLP.
    #pragma unroll 4
    for (int i = threadIdx.x; i < PER_CHUNK; i += TPB) {
        float4 pv = __ldcs(&p[i]);   // streaming: read-once data
        float4 tv = __ldcs(&t[i]);
        kl_acc(pv.x, tv.x, sp, st, d);
        kl_acc(pv.y, tv.y, sp, st, d);
        kl_acc(pv.z, tv.z, sp, st, d);
        kl_acc(pv.w, tv.w, sp, st, d);
    }

    // Warp reduce (3 values).
    #pragma unroll
    for (int o = 16; o > 0; o >>= 1) {
        sp += __shfl_down_sync(0xFFFFFFFFu, sp, o);
        st += __shfl_down_sync(0xFFFFFFFFu, st, o);
        d  += __shfl_down_sync(0xFFFFFFFFu, d,  o);
    }

    __shared__ float s_sp[TPB / 32];
    __shared__ float s_st[TPB / 32];
    __shared__ float s_d [TPB / 32];
    __shared__ bool  s_last;
    const int wid = threadIdx.x >> 5;
    const int lid = threadIdx.x & 31;
    if (lid == 0) { s_sp[wid] = sp; s_st[wid] = st; s_d[wid] = d; }
    __syncthreads();

    if (threadIdx.x == 0) {
        float bsp = 0.f, bst = 0.f, bd = 0.f;
        #pragma unroll
        for (int w = 0; w < TPB / 32; w++) { bsp += s_sp[w]; bst += s_st[w]; bd += s_d[w]; }
        g_partial[blk * 3 + 0] = bsp;
        g_partial[blk * 3 + 1] = bst;
        g_partial[blk * 3 + 2] = bd;
        __threadfence();
        unsigned int prev = atomicAdd(&g_done, 1u);
        s_last = (prev == (unsigned int)(GRID - 1));
    }
    __syncthreads();

    if (!s_last) return;

    // ---- Finalize: only the last-arriving block runs this. ----
    __shared__ float s_kl[B];
    const int tid = threadIdx.x;

    // Zero the (poisoned) output buffer.
    for (int i = tid; i < out_size; i += TPB) out[i] = 0.f;

    if (tid < B) {
        float fsp = 0.f, fst = 0.f, fd = 0.f;
        #pragma unroll
        for (int c = 0; c < CPB; c++) {
            const int idx = (tid * CPB + c) * 3;
            fsp += g_partial[idx + 0];
            fst += g_partial[idx + 1];
            fd  += g_partial[idx + 2];
        }
        s_kl[tid] = (fd * LN2F) / fst + logf(fsp / fst);
    }
    __syncthreads();

    if (tid == 0) {
        float acc = 0.f;
        #pragma unroll
        for (int i = 0; i < B; i++) acc += s_kl[i];
        out[0] = acc * (1.0f / (float)B);
        g_done = 0;   // reset for next graph replay
    }
}

extern "C" void kernel_launch(void* const* d_in, const int* in_sizes, int n_in,
                              void* d_out, int out_size) {
    const float4* pred = (const float4*)d_in[0];
    const float4* tru  = (const float4*)d_in[1];
    float* out = (float*)d_out;

    kl_fused<<<GRID, TPB>>>(pred, tru, out, out_size);
}

// round 3
// speedup vs baseline: 1.1714x; 1.1714x over previous
#include <cuda_runtime.h>
#include <cuda_bf16.h>

// KLDivergence fused single-kernel, MLP-batched loads.
// pred_map, true_map: [64, 512, 512] fp32.
// KL_b = D_b/S_t_b + ln(S_p_b/S_t_b), with
//   S_p = sum(p+eps), S_t = sum(t+eps), D = sum((t+eps)*(ln(t+eps)-ln(p+eps)))
// D accumulated in log2 units; scaled by ln2 in the finalize.
// Output = mean over 64 batches.

#define KL_EPS 1e-6f
#define LN2F   0.6931471805599453f

static constexpr int B         = 64;
static constexpr int N_PER_B   = 512 * 512;        // 262144
static constexpr int V4_PER_B  = N_PER_B / 4;      // 65536 float4 per batch
static constexpr int CPB       = 16;               // chunks (blocks) per batch
static constexpr int TPB       = 256;
static constexpr int GRID      = B * CPB;          // 1024 blocks
static constexpr int PER_CHUNK = V4_PER_B / CPB;   // 4096 float4 per chunk
static constexpr int ITERS     = PER_CHUNK / TPB;  // 16 float4 per thread
static constexpr int U         = 4;                // batched loads per round (8 LDG.128)

// Deterministic scratch: per-(batch,chunk) partials of (S_p, S_t, D_lg2).
__device__ float g_partial[GRID * 3];
__device__ unsigned int g_done = 0;

__device__ __forceinline__ void kl_acc(float p, float t,
                                       float& sp, float& st, float& d) {
    float pp = p + KL_EPS;
    float tt = t + KL_EPS;
    sp += pp;
    st += tt;
    d  += tt * (__log2f(tt) - __log2f(pp));   // ln2 scale deferred to finalize
}

__global__ __launch_bounds__(TPB)
void kl_fused(const float4* __restrict__ pred, const float4* __restrict__ tru,
              float* __restrict__ out, int out_size) {
    const int blk   = blockIdx.x;
    const int batch = blk / CPB;
    const int chunk = blk % CPB;

    const float4* pb = pred + (size_t)batch * V4_PER_B + (size_t)chunk * PER_CHUNK
                            + threadIdx.x;
    const float4* tb = tru  + (size_t)batch * V4_PER_B + (size_t)chunk * PER_CHUNK
                            + threadIdx.x;

    // 2-way split accumulators to shorten serial FADD chains.
    float sp0 = 0.f, sp1 = 0.f, st0 = 0.f, st1 = 0.f, d0 = 0.f, d1 = 0.f;

    #pragma unroll 1
    for (int ii = 0; ii < ITERS; ii += U) {
        // Phase 1: batch all loads (8x LDG.128 front-batched -> MLP ~8/warp).
        float4 pv[U], tv[U];
        #pragma unroll
        for (int u = 0; u < U; u++) {
            pv[u] = pb[(size_t)(ii + u) * TPB];
            tv[u] = tb[(size_t)(ii + u) * TPB];
        }
        // Phase 2: compute.
        #pragma unroll
        for (int u = 0; u < U; u++) {
            kl_acc(pv[u].x, tv[u].x, sp0, st0, d0);
            kl_acc(pv[u].y, tv[u].y, sp1, st1, d1);
            kl_acc(pv[u].z, tv[u].z, sp0, st0, d0);
            kl_acc(pv[u].w, tv[u].w, sp1, st1, d1);
        }
    }

    float sp = sp0 + sp1, st = st0 + st1, d = d0 + d1;

    // Warp reduce (3 values).
    #pragma unroll
    for (int o = 16; o > 0; o >>= 1) {
        sp += __shfl_down_sync(0xFFFFFFFFu, sp, o);
        st += __shfl_down_sync(0xFFFFFFFFu, st, o);
        d  += __shfl_down_sync(0xFFFFFFFFu, d,  o);
    }

    __shared__ float s_sp[TPB / 32];
    __shared__ float s_st[TPB / 32];
    __shared__ float s_d [TPB / 32];
    __shared__ bool  s_last;
    const int wid = threadIdx.x >> 5;
    const int lid = threadIdx.x & 31;
    if (lid == 0) { s_sp[wid] = sp; s_st[wid] = st; s_d[wid] = d; }
    __syncthreads();

    if (threadIdx.x == 0) {
        float bsp = 0.f, bst = 0.f, bd = 0.f;
        #pragma unroll
        for (int w = 0; w < TPB / 32; w++) { bsp += s_sp[w]; bst += s_st[w]; bd += s_d[w]; }
        g_partial[blk * 3 + 0] = bsp;
        g_partial[blk * 3 + 1] = bst;
        g_partial[blk * 3 + 2] = bd;
        __threadfence();
        unsigned int prev = atomicAdd(&g_done, 1u);
        s_last = (prev == (unsigned int)(GRID - 1));
    }
    __syncthreads();

    if (!s_last) return;

    // ---- Finalize: only the last-arriving block runs this. ----
    __shared__ float s_kl[B];
    const int tid = threadIdx.x;

    // Zero the (poisoned) output buffer.
    for (int i = tid; i < out_size; i += TPB) out[i] = 0.f;

    if (tid < B) {
        float fsp = 0.f, fst = 0.f, fd = 0.f;
        #pragma unroll
        for (int c = 0; c < CPB; c++) {
            const int idx = (tid * CPB + c) * 3;
            fsp += g_partial[idx + 0];
            fst += g_partial[idx + 1];
            fd  += g_partial[idx + 2];
        }
        s_kl[tid] = (fd * LN2F) / fst + logf(fsp / fst);
    }
    __syncthreads();

    if (tid == 0) {
        float acc = 0.f;
        #pragma unroll
        for (int i = 0; i < B; i++) acc += s_kl[i];
        out[0] = acc * (1.0f / (float)B);
        g_done = 0;   // reset for next graph replay
    }
}

extern "C" void kernel_launch(void* const* d_in, const int* in_sizes, int n_in,
                              void* d_out, int out_size) {
    const float4* pred = (const float4*)d_in[0];
    const float4* tru  = (const float4*)d_in[1];
    float* out = (float*)d_out;

    kl_fused<<<GRID, TPB>>>(pred, tru, out, out_size);
}

// round 4
// speedup vs baseline: 1.1727x; 1.0011x over previous
#include <cuda_runtime.h>
#include <cuda_bf16.h>

// KLDivergence fused single-kernel, asm-forced MLP batching.
// pred_map, true_map: [64, 512, 512] fp32.
// KL_b = D_b/S_t_b + ln(S_p_b/S_t_b), with
//   S_p = sum(p+eps), S_t = sum(t+eps), D = sum((t+eps)*(ln(t+eps)-ln(p+eps)))
// D accumulated in log2 units; ln2 scale applied in finalize.
// Output = mean over 64 batches.

#define KL_EPS 1e-6f
#define LN2F   0.6931471805599453f

static constexpr int B         = 64;
static constexpr int N_PER_B   = 512 * 512;        // 262144
static constexpr int V4_PER_B  = N_PER_B / 4;      // 65536 float4 per batch
static constexpr int CPB       = 16;               // chunks (blocks) per batch
static constexpr int TPB       = 128;
static constexpr int GRID      = B * CPB;          // 1024 blocks (all resident @8/SM)
static constexpr int PER_CHUNK = V4_PER_B / CPB;   // 4096 float4 per chunk
static constexpr int ITERS     = PER_CHUNK / TPB;  // 32 float4 per thread
static constexpr int U         = 4;                // pairs per round -> 8 LDG.128 in flight
static constexpr int ROUNDS    = ITERS / U;        // 8

// Deterministic scratch: per-(batch,chunk) partials of (S_p, S_t, D_lg2).
__device__ float g_partial[GRID * 3];
__device__ unsigned int g_done = 0;

// Volatile PTX load: cannot be sunk/rematerialized by ptxas -> stays front-batched.
__device__ __forceinline__ float4 ldg4(const float4* p) {
    float4 v;
    asm volatile("ld.global.nc.v4.f32 {%0,%1,%2,%3}, [%4];"
                 : "=f"(v.x), "=f"(v.y), "=f"(v.z), "=f"(v.w)
                 : "l"(p));
    return v;
}

__device__ __forceinline__ void kl_acc(float p, float t,
                                       float& sp, float& st, float& d) {
    float pp = p + KL_EPS;
    float tt = t + KL_EPS;
    sp += pp;
    st += tt;
    d  += tt * (__log2f(tt) - __log2f(pp));   // ln2 scale deferred to finalize
}

__global__ __launch_bounds__(TPB, 8)
void kl_fused(const float4* __restrict__ pred, const float4* __restrict__ tru,
              float* __restrict__ out, int out_size) {
    const int blk   = blockIdx.x;
    const int batch = blk / CPB;
    const int chunk = blk % CPB;

    const float4* pb = pred + (size_t)batch * V4_PER_B + (size_t)chunk * PER_CHUNK
                            + threadIdx.x;
    const float4* tb = tru  + (size_t)batch * V4_PER_B + (size_t)chunk * PER_CHUNK
                            + threadIdx.x;

    float sp0 = 0.f, sp1 = 0.f, st0 = 0.f, st1 = 0.f, d0 = 0.f, d1 = 0.f;

    #pragma unroll 1
    for (int r = 0; r < ROUNDS; r++) {
        // Phase 1: 8 LDG.128 issued back-to-back (forced by asm volatile).
        float4 p0 = ldg4(pb + 0 * TPB);
        float4 t0 = ldg4(tb + 0 * TPB);
        float4 p1 = ldg4(pb + 1 * TPB);
        float4 t1 = ldg4(tb + 1 * TPB);
        float4 p2 = ldg4(pb + 2 * TPB);
        float4 t2 = ldg4(tb + 2 * TPB);
        float4 p3 = ldg4(pb + 3 * TPB);
        float4 t3 = ldg4(tb + 3 * TPB);
        pb += U * TPB;
        tb += U * TPB;

        // Phase 2: compute (2-way split accumulators).
        kl_acc(p0.x, t0.x, sp0, st0, d0);
        kl_acc(p0.y, t0.y, sp1, st1, d1);
        kl_acc(p0.z, t0.z, sp0, st0, d0);
        kl_acc(p0.w, t0.w, sp1, st1, d1);
        kl_acc(p1.x, t1.x, sp0, st0, d0);
        kl_acc(p1.y, t1.y, sp1, st1, d1);
        kl_acc(p1.z, t1.z, sp0, st0, d0);
        kl_acc(p1.w, t1.w, sp1, st1, d1);
        kl_acc(p2.x, t2.x, sp0, st0, d0);
        kl_acc(p2.y, t2.y, sp1, st1, d1);
        kl_acc(p2.z, t2.z, sp0, st0, d0);
        kl_acc(p2.w, t2.w, sp1, st1, d1);
        kl_acc(p3.x, t3.x, sp0, st0, d0);
        kl_acc(p3.y, t3.y, sp1, st1, d1);
        kl_acc(p3.z, t3.z, sp0, st0, d0);
        kl_acc(p3.w, t3.w, sp1, st1, d1);
    }

    float sp = sp0 + sp1, st = st0 + st1, d = d0 + d1;

    // Warp reduce (3 values).
    #pragma unroll
    for (int o = 16; o > 0; o >>= 1) {
        sp += __shfl_down_sync(0xFFFFFFFFu, sp, o);
        st += __shfl_down_sync(0xFFFFFFFFu, st, o);
        d  += __shfl_down_sync(0xFFFFFFFFu, d,  o);
    }

    __shared__ float s_sp[TPB / 32];
    __shared__ float s_st[TPB / 32];
    __shared__ float s_d [TPB / 32];
    __shared__ bool  s_last;
    const int wid = threadIdx.x >> 5;
    const int lid = threadIdx.x & 31;
    if (lid == 0) { s_sp[wid] = sp; s_st[wid] = st; s_d[wid] = d; }
    __syncthreads();

    if (threadIdx.x == 0) {
        float bsp = 0.f, bst = 0.f, bd = 0.f;
        #pragma unroll
        for (int w = 0; w < TPB / 32; w++) { bsp += s_sp[w]; bst += s_st[w]; bd += s_d[w]; }
        g_partial[blk * 3 + 0] = bsp;
        g_partial[blk * 3 + 1] = bst;
        g_partial[blk * 3 + 2] = bd;
        __threadfence();
        unsigned int prev = atomicAdd(&g_done, 1u);
        s_last = (prev == (unsigned int)(GRID - 1));
    }
    __syncthreads();

    if (!s_last) return;

    // ---- Finalize: only the last-arriving block runs this. ----
    __shared__ float s_kl[B];
    const int tid = threadIdx.x;

    // Zero the (poisoned) output buffer.
    for (int i = tid; i < out_size; i += TPB) out[i] = 0.f;

    if (tid < B) {
        float fsp = 0.f, fst = 0.f, fd = 0.f;
        #pragma unroll
        for (int c = 0; c < CPB; c++) {
            const int idx = (tid * CPB + c) * 3;
            fsp += g_partial[idx + 0];
            fst += g_partial[idx + 1];
            fd  += g_partial[idx + 2];
        }
        s_kl[tid] = (fd * LN2F) / fst + logf(fsp / fst);
    }
    __syncthreads();

    if (tid == 0) {
        float acc = 0.f;
        #pragma unroll
        for (int i = 0; i < B; i++) acc += s_kl[i];
        out[0] = acc * (1.0f / (float)B);
        g_done = 0;   // reset for next graph replay
    }
}

extern "C" void kernel_launch(void* const* d_in, const int* in_sizes, int n_in,
                              void* d_out, int out_size) {
    const float4* pred = (const float4*)d_in[0];
    const float4* tru  = (const float4*)d_in[1];
    float* out = (float*)d_out;

    kl_fused<<<GRID, TPB>>>(pred, tru, out, out_size);
}